// round 1
// baseline (speedup 1.0000x reference)
#include <cuda_runtime.h>
#include <cuda_bf16.h>

// Problem constants
#define B_    2
#define H_    16
#define S_    2048
#define D_    64
#define DM    1024
#define MTOT  4096   // B_*S_

static const long OUT_ELEMS  = (long)MTOT * DM;            // 4,194,304
static const long ATTN_ELEMS = (long)B_ * H_ * S_ * S_;    // 134,217,728

// Scratch (device-global; no runtime allocation allowed)
__device__ float g_q[B_*H_*S_*D_];
__device__ float g_k[B_*H_*S_*D_];
__device__ float g_v[B_*H_*S_*D_];
__device__ float g_ctx[MTOT*DM];
__device__ float g_attn[(size_t)B_*H_*S_*S_];

// ---------------------------------------------------------------------------
// K1/K5: C[4096,1024] = A[4096,1024] @ W[1024,1024] + bias
// SPLIT=1: scatter output to [B,H,S,D] layout
// ---------------------------------------------------------------------------
template<int SPLIT>
__global__ __launch_bounds__(256)
void sgemm_bias(const float* __restrict__ A, const float* __restrict__ W,
                const float* __restrict__ bias, float* __restrict__ C) {
    const int BM = 128, BN = 128, BK = 16;
    __shared__ float As[16][128];   // transposed: As[k][m]
    __shared__ float Bs[16][128];   // Bs[k][n]
    const int tid = threadIdx.x;
    const int bx = blockIdx.x, by = blockIdx.y;
    const int tx = tid & 15, ty = tid >> 4;
    float acc[8][8];
    #pragma unroll
    for (int i = 0; i < 8; i++)
        #pragma unroll
        for (int j = 0; j < 8; j++) acc[i][j] = 0.f;

    const float* Ab = A + (long)by * BM * DM;

    for (int k0 = 0; k0 < DM; k0 += BK) {
        // A tile 128x16 : 512 float4, 2 per thread
        #pragma unroll
        for (int l = 0; l < 2; l++) {
            int f = tid + l * 256;
            int r = f >> 2;
            int c = (f & 3) * 4;
            float4 v = *reinterpret_cast<const float4*>(Ab + (long)r * DM + k0 + c);
            As[c+0][r] = v.x; As[c+1][r] = v.y; As[c+2][r] = v.z; As[c+3][r] = v.w;
        }
        // W tile 16x128
        #pragma unroll
        for (int l = 0; l < 2; l++) {
            int f = tid + l * 256;
            int r = f >> 5;
            int c = (f & 31) * 4;
            *reinterpret_cast<float4*>(&Bs[r][c]) =
                *reinterpret_cast<const float4*>(W + (long)(k0 + r) * DM + bx * BN + c);
        }
        __syncthreads();
        #pragma unroll
        for (int k = 0; k < BK; k++) {
            float4 a0 = *reinterpret_cast<const float4*>(&As[k][ty*8]);
            float4 a1 = *reinterpret_cast<const float4*>(&As[k][ty*8+4]);
            float4 b0 = *reinterpret_cast<const float4*>(&Bs[k][tx*8]);
            float4 b1 = *reinterpret_cast<const float4*>(&Bs[k][tx*8+4]);
            float ra[8] = {a0.x,a0.y,a0.z,a0.w,a1.x,a1.y,a1.z,a1.w};
            float rb[8] = {b0.x,b0.y,b0.z,b0.w,b1.x,b1.y,b1.z,b1.w};
            #pragma unroll
            for (int i = 0; i < 8; i++)
                #pragma unroll
                for (int j = 0; j < 8; j++)
                    acc[i][j] = fmaf(ra[i], rb[j], acc[i][j]);
        }
        __syncthreads();
    }

    #pragma unroll
    for (int i = 0; i < 8; i++) {
        int m = by * BM + ty * 8 + i;
        #pragma unroll
        for (int j = 0; j < 8; j++) {
            int n = bx * BN + tx * 8 + j;
            float v = acc[i][j] + bias[n];
            if (SPLIT) {
                int b = m / S_, s = m - b * S_;
                int h = n >> 6, d = n & 63;
                C[(((long)(b * H_ + h)) * S_ + s) * D_ + d] = v;
            } else {
                C[(long)m * DM + n] = v;
            }
        }
    }
}

// ---------------------------------------------------------------------------
// K2: per (b,h): scores[S,S] = Q[S,64] @ K[S,64]^T * (1/8)
// ---------------------------------------------------------------------------
__global__ __launch_bounds__(256)
void scores_kernel(const float* __restrict__ Qh, const float* __restrict__ Kh,
                   float* __restrict__ attn) {
    const int BM = 128, BN = 128, BK = 32;
    __shared__ float As[32][132];
    __shared__ float Bs[32][132];
    const int bh = blockIdx.z;
    const int tid = threadIdx.x;
    const int tx = tid & 15, ty = tid >> 4;
    const float* Qb = Qh + ((long)bh * S_ + (long)blockIdx.y * BM) * D_;
    const float* Kb = Kh + ((long)bh * S_ + (long)blockIdx.x * BN) * D_;
    float acc[8][8];
    #pragma unroll
    for (int i = 0; i < 8; i++)
        #pragma unroll
        for (int j = 0; j < 8; j++) acc[i][j] = 0.f;

    for (int k0 = 0; k0 < D_; k0 += BK) {
        #pragma unroll
        for (int l = 0; l < 4; l++) {
            int f = tid + l * 256;
            int r = f >> 3;
            int c = (f & 7) * 4;
            float4 va = *reinterpret_cast<const float4*>(Qb + (long)r * D_ + k0 + c);
            As[c+0][r] = va.x; As[c+1][r] = va.y; As[c+2][r] = va.z; As[c+3][r] = va.w;
            float4 vb = *reinterpret_cast<const float4*>(Kb + (long)r * D_ + k0 + c);
            Bs[c+0][r] = vb.x; Bs[c+1][r] = vb.y; Bs[c+2][r] = vb.z; Bs[c+3][r] = vb.w;
        }
        __syncthreads();
        #pragma unroll
        for (int k = 0; k < BK; k++) {
            float4 a0 = *reinterpret_cast<const float4*>(&As[k][ty*8]);
            float4 a1 = *reinterpret_cast<const float4*>(&As[k][ty*8+4]);
            float4 b0 = *reinterpret_cast<const float4*>(&Bs[k][tx*8]);
            float4 b1 = *reinterpret_cast<const float4*>(&Bs[k][tx*8+4]);
            float ra[8] = {a0.x,a0.y,a0.z,a0.w,a1.x,a1.y,a1.z,a1.w};
            float rb[8] = {b0.x,b0.y,b0.z,b0.w,b1.x,b1.y,b1.z,b1.w};
            #pragma unroll
            for (int i = 0; i < 8; i++)
                #pragma unroll
                for (int j = 0; j < 8; j++)
                    acc[i][j] = fmaf(ra[i], rb[j], acc[i][j]);
        }
        __syncthreads();
    }

    float* Cb = attn + (long)bh * S_ * S_ + (long)(blockIdx.y * BM) * S_ + blockIdx.x * BN;
    #pragma unroll
    for (int i = 0; i < 8; i++) {
        #pragma unroll
        for (int j = 0; j < 8; j += 4) {
            float4 o;
            o.x = acc[i][j+0] * 0.125f;
            o.y = acc[i][j+1] * 0.125f;
            o.z = acc[i][j+2] * 0.125f;
            o.w = acc[i][j+3] * 0.125f;
            *reinterpret_cast<float4*>(&Cb[(long)(ty*8 + i) * S_ + tx*8 + j]) = o;
        }
    }
}

// ---------------------------------------------------------------------------
// K3: row softmax over attn, with mask (mask==1 -> -1e9), in place.
// One block per row (B*H*S rows), 256 threads, 8 elems/thread.
// ---------------------------------------------------------------------------
__global__ __launch_bounds__(256)
void softmax_kernel(float* __restrict__ attn, const float* __restrict__ mask) {
    const long row = blockIdx.x;
    const int b = (int)(row >> 15);                 // / (H_*S_) = / 32768
    float* p = attn + row * S_;
    const float* mrow = mask + (long)b * S_;
    const int tid = threadIdx.x;

    float vals[8];
    #pragma unroll
    for (int l = 0; l < 2; l++) {
        float4 x  = reinterpret_cast<const float4*>(p)[tid + l*256];
        float4 mm = reinterpret_cast<const float4*>(mrow)[tid + l*256];
        vals[l*4+0] = x.x - 1e9f * mm.x;
        vals[l*4+1] = x.y - 1e9f * mm.y;
        vals[l*4+2] = x.z - 1e9f * mm.z;
        vals[l*4+3] = x.w - 1e9f * mm.w;
    }
    float mx = -3.0e38f;
    #pragma unroll
    for (int i = 0; i < 8; i++) mx = fmaxf(mx, vals[i]);

    __shared__ float red[8];
    #pragma unroll
    for (int o = 16; o > 0; o >>= 1) mx = fmaxf(mx, __shfl_xor_sync(0xFFFFFFFFu, mx, o));
    if ((tid & 31) == 0) red[tid >> 5] = mx;
    __syncthreads();
    if (tid < 32) {
        float m2 = (tid < 8) ? red[tid] : -3.0e38f;
        #pragma unroll
        for (int o = 4; o > 0; o >>= 1) m2 = fmaxf(m2, __shfl_xor_sync(0xFFFFFFFFu, m2, o));
        if (tid == 0) red[0] = m2;
    }
    __syncthreads();
    mx = red[0];
    __syncthreads();

    float sum = 0.f;
    #pragma unroll
    for (int i = 0; i < 8; i++) { vals[i] = __expf(vals[i] - mx); sum += vals[i]; }
    #pragma unroll
    for (int o = 16; o > 0; o >>= 1) sum += __shfl_xor_sync(0xFFFFFFFFu, sum, o);
    if ((tid & 31) == 0) red[tid >> 5] = sum;
    __syncthreads();
    if (tid < 32) {
        float s2 = (tid < 8) ? red[tid] : 0.f;
        #pragma unroll
        for (int o = 4; o > 0; o >>= 1) s2 += __shfl_xor_sync(0xFFFFFFFFu, s2, o);
        if (tid == 0) red[0] = s2;
    }
    __syncthreads();
    const float inv = 1.f / red[0];

    #pragma unroll
    for (int l = 0; l < 2; l++) {
        float4 x;
        x.x = vals[l*4+0] * inv;
        x.y = vals[l*4+1] * inv;
        x.z = vals[l*4+2] * inv;
        x.w = vals[l*4+3] * inv;
        reinterpret_cast<float4*>(p)[tid + l*256] = x;
    }
}

// ---------------------------------------------------------------------------
// K4: per (b,h): ctx_h[S,64] = attn[S,S] @ V[S,64], written merged-heads
// into ctx[B*S, 1024] at column h*64.
// ---------------------------------------------------------------------------
__global__ __launch_bounds__(256)
void context_kernel(const float* __restrict__ attn, const float* __restrict__ Vh,
                    float* __restrict__ ctx) {
    const int BM = 64, BN = 64, BK = 32;
    __shared__ float Ps[64][36];
    __shared__ float Vs[32][68];
    const int bh = blockIdx.z;
    const int tid = threadIdx.x;
    const int tx = tid & 15, ty = tid >> 4;
    const float* Pb = attn + (long)bh * S_ * S_ + (long)blockIdx.y * BM * S_;
    const float* Vb = Vh + (long)bh * S_ * D_;
    float acc[4][4];
    #pragma unroll
    for (int i = 0; i < 4; i++)
        #pragma unroll
        for (int j = 0; j < 4; j++) acc[i][j] = 0.f;

    for (int k0 = 0; k0 < S_; k0 += BK) {
        #pragma unroll
        for (int l = 0; l < 2; l++) {
            int f = tid + l * 256;
            int r = f >> 3;
            int c = (f & 7) * 4;
            *reinterpret_cast<float4*>(&Ps[r][c]) =
                *reinterpret_cast<const float4*>(Pb + (long)r * S_ + k0 + c);
            int r2 = f >> 4;
            int c2 = (f & 15) * 4;
            *reinterpret_cast<float4*>(&Vs[r2][c2]) =
                *reinterpret_cast<const float4*>(Vb + (long)(k0 + r2) * D_ + c2);
        }
        __syncthreads();
        #pragma unroll
        for (int k = 0; k < BK; k++) {
            float ra[4];
            #pragma unroll
            for (int i = 0; i < 4; i++) ra[i] = Ps[ty*4 + i][k];
            float4 rb = *reinterpret_cast<const float4*>(&Vs[k][tx*4]);
            #pragma unroll
            for (int i = 0; i < 4; i++) {
                acc[i][0] = fmaf(ra[i], rb.x, acc[i][0]);
                acc[i][1] = fmaf(ra[i], rb.y, acc[i][1]);
                acc[i][2] = fmaf(ra[i], rb.z, acc[i][2]);
                acc[i][3] = fmaf(ra[i], rb.w, acc[i][3]);
            }
        }
        __syncthreads();
    }

    const int b = bh >> 4, h = bh & 15;
    const int m0 = blockIdx.y * BM;
    #pragma unroll
    for (int i = 0; i < 4; i++) {
        long rowb = ((long)b * S_ + m0 + ty*4 + i) * DM + h * 64;
        float4 o; o.x = acc[i][0]; o.y = acc[i][1]; o.z = acc[i][2]; o.w = acc[i][3];
        *reinterpret_cast<float4*>(&ctx[rowb + tx*4]) = o;
    }
}

// ---------------------------------------------------------------------------
extern "C" void kernel_launch(void* const* d_in, const int* in_sizes, int n_in,
                              void* d_out, int out_size) {
    const float* Q    = (const float*)d_in[0];
    const float* K    = (const float*)d_in[1];
    const float* V    = (const float*)d_in[2];
    const float* mask = (const float*)d_in[3];
    const float* Wq   = (const float*)d_in[4];
    const float* bq   = (const float*)d_in[5];
    const float* Wk   = (const float*)d_in[6];
    const float* bk   = (const float*)d_in[7];
    const float* Wv   = (const float*)d_in[8];
    const float* bv   = (const float*)d_in[9];
    const float* Wo   = (const float*)d_in[10];
    const float* bo   = (const float*)d_in[11];
    float* out = (float*)d_out;

    float *qp, *kp, *vp, *cp, *ap;
    cudaGetSymbolAddress((void**)&qp, g_q);
    cudaGetSymbolAddress((void**)&kp, g_k);
    cudaGetSymbolAddress((void**)&vp, g_v);
    cudaGetSymbolAddress((void**)&cp, g_ctx);
    cudaGetSymbolAddress((void**)&ap, g_attn);

    // If the harness wants the (out, attn) tuple concatenated, write attn
    // directly into its slot in d_out; otherwise use scratch.
    float* attn = ((long)out_size >= OUT_ELEMS + ATTN_ELEMS) ? (out + OUT_ELEMS) : ap;

    dim3 g1(DM / 128, MTOT / 128);
    sgemm_bias<1><<<g1, 256>>>(Q, Wq, bq, qp);
    sgemm_bias<1><<<g1, 256>>>(K, Wk, bk, kp);
    sgemm_bias<1><<<g1, 256>>>(V, Wv, bv, vp);

    dim3 g2(S_ / 128, S_ / 128, B_ * H_);
    scores_kernel<<<g2, 256>>>(qp, kp, attn);

    softmax_kernel<<<B_ * H_ * S_, 256>>>(attn, mask);

    dim3 g4(1, S_ / 64, B_ * H_);
    context_kernel<<<g4, 256>>>(attn, vp, cp);

    sgemm_bias<0><<<g1, 256>>>(cp, Wo, bo, out);
}

// round 2
// speedup vs baseline: 2.4388x; 2.4388x over previous
#include <cuda_runtime.h>
#include <cuda_bf16.h>

// Problem constants
#define B_    2
#define H_    16
#define S_    2048
#define D_    64
#define DM    1024
#define MTOT  4096   // B_*S_

static const long OUT_ELEMS  = (long)MTOT * DM;            // 4,194,304
static const long ATTN_ELEMS = (long)B_ * H_ * S_ * S_;    // 134,217,728

// Scratch (device-global; no runtime allocation allowed)
__device__ float g_q[B_*H_*S_*D_];
__device__ float g_k[B_*H_*S_*D_];
__device__ float g_v[B_*H_*S_*D_];
__device__ float g_ctx[MTOT*DM];
__device__ float g_attn[(size_t)B_*H_*S_*S_];

// ---------------------------------------------------------------------------
// tf32 helpers
// ---------------------------------------------------------------------------
__device__ __forceinline__ float tf(float f) {
    unsigned u;
    asm("cvt.rna.tf32.f32 %0, %1;" : "=r"(u) : "f"(f));
    return __uint_as_float(u);
}

__device__ __forceinline__ void mma_tf32(
    float& c0, float& c1, float& c2, float& c3,
    unsigned a0, unsigned a1, unsigned a2, unsigned a3,
    unsigned b0, unsigned b1)
{
    asm volatile(
        "mma.sync.aligned.m16n8k8.row.col.f32.tf32.tf32.f32 "
        "{%0,%1,%2,%3},{%4,%5,%6,%7},{%8,%9},{%0,%1,%2,%3};"
        : "+f"(c0), "+f"(c1), "+f"(c2), "+f"(c3)
        : "r"(a0), "r"(a1), "r"(a2), "r"(a3), "r"(b0), "r"(b1));
}

// Smem layout constants
// A-style (K-major source; frag pairs (c, c+4) adjacent):
//   As[chunk][m][8], chunk stride 1026 floats (pad 2 for STS bank spread)
// W-style (N-major source): Bs[chunk][kk][132], chunk stride 1056 floats
#define CSA 1026
#define RSB 132
#define CSB 1056

// ---------------------------------------------------------------------------
// K1/K5: C[4096,1024] = A[4096,1024] @ W[1024,1024] + bias   (tf32 MMA)
// SPLIT=1: scatter output to [B,H,S,D]
// BM=128 BN=128 BK=32, 8 warps (2M x 4N), warp tile 64x32
// ---------------------------------------------------------------------------
template<int SPLIT>
__global__ __launch_bounds__(256)
void gemm_tc(const float* __restrict__ A, const float* __restrict__ W,
             const float* __restrict__ bias, float* __restrict__ C)
{
    extern __shared__ float sm[];
    float* As = sm;           // 2 bufs * 4*CSA = 8208
    float* Bs = sm + 8208;    // 2 bufs * 4*CSB = 8448

    const int tid = threadIdx.x, lane = tid & 31, warp = tid >> 5;
    const int wm = warp >> 2, wn = warp & 3;
    const int bx = blockIdx.x, by = blockIdx.y;
    const float* Ab = A + (long)by * 128 * DM;
    const float* Wb = W + (long)bx * 128;

    const int a_ch = tid & 3, a_m = tid >> 2;   // A: thread owns 8-k chunk of one row
    const int b_cg = tid & 31, b_k = tid >> 5;  // B: thread owns 4 n of one k-row

    float acc[4][4][4];
    #pragma unroll
    for (int i = 0; i < 4; i++)
        #pragma unroll
        for (int j = 0; j < 4; j++)
            #pragma unroll
            for (int q = 0; q < 4; q++) acc[i][j][q] = 0.f;

    float4 ar[2][2], br[4];
    const int b_kk = 2 * (b_k & 3) + ((b_k >> 2) & 1);

    // prologue: LDG k0=0
    #pragma unroll
    for (int p = 0; p < 2; p++) {
        const float* s = Ab + (long)(a_m + 64 * p) * DM + a_ch * 8;
        ar[p][0] = *(const float4*)s;
        ar[p][1] = *(const float4*)(s + 4);
    }
    #pragma unroll
    for (int p = 0; p < 4; p++)
        br[p] = *(const float4*)(Wb + (long)(b_k + 8 * p) * DM + b_cg * 4);

    // STS buf 0
    {
        #pragma unroll
        for (int p = 0; p < 2; p++) {
            float* d = As + a_ch * CSA + (a_m + 64 * p) * 8;
            float v0[4] = {ar[p][0].x, ar[p][0].y, ar[p][0].z, ar[p][0].w};
            float v1[4] = {ar[p][1].x, ar[p][1].y, ar[p][1].z, ar[p][1].w};
            #pragma unroll
            for (int j = 0; j < 4; j++) {
                float2 t; t.x = tf(v0[j]); t.y = tf(v1[j]);
                *(float2*)(d + 2 * j) = t;
            }
        }
        #pragma unroll
        for (int p = 0; p < 4; p++) {
            float* d = Bs + p * CSB + b_kk * RSB + b_cg * 4;
            float4 t;
            t.x = tf(br[p].x); t.y = tf(br[p].y); t.z = tf(br[p].z); t.w = tf(br[p].w);
            *(float4*)d = t;
        }
    }
    __syncthreads();

    const int NK = DM / 32;  // 32
    for (int it = 0; it < NK; ++it) {
        const bool pre = (it + 1 < NK);
        if (pre) {
            const int k0 = (it + 1) * 32;
            #pragma unroll
            for (int p = 0; p < 2; p++) {
                const float* s = Ab + (long)(a_m + 64 * p) * DM + k0 + a_ch * 8;
                ar[p][0] = *(const float4*)s;
                ar[p][1] = *(const float4*)(s + 4);
            }
            #pragma unroll
            for (int p = 0; p < 4; p++)
                br[p] = *(const float4*)(Wb + (long)(k0 + b_k + 8 * p) * DM + b_cg * 4);
        }

        const float* Ac = As + (it & 1) * 4104;
        const float* Bc = Bs + (it & 1) * 4224;
        #pragma unroll
        for (int ch = 0; ch < 4; ch++) {
            unsigned a[4][4], b[4][2];
            #pragma unroll
            for (int mi = 0; mi < 4; mi++) {
                int r = wm * 64 + mi * 16 + (lane >> 2);
                float2 lo = *(const float2*)(Ac + ch * CSA + r * 8 + 2 * (lane & 3));
                float2 hi = *(const float2*)(Ac + ch * CSA + (r + 8) * 8 + 2 * (lane & 3));
                a[mi][0] = __float_as_uint(lo.x); a[mi][1] = __float_as_uint(hi.x);
                a[mi][2] = __float_as_uint(lo.y); a[mi][3] = __float_as_uint(hi.y);
            }
            #pragma unroll
            for (int ni = 0; ni < 4; ni++) {
                int n = wn * 32 + ni * 8 + (lane >> 2);
                int c2 = 2 * (lane & 3);
                b[ni][0] = __float_as_uint(Bc[ch * CSB + c2 * RSB + n]);
                b[ni][1] = __float_as_uint(Bc[ch * CSB + (c2 + 1) * RSB + n]);
            }
            #pragma unroll
            for (int mi = 0; mi < 4; mi++)
                #pragma unroll
                for (int ni = 0; ni < 4; ni++)
                    mma_tf32(acc[mi][ni][0], acc[mi][ni][1], acc[mi][ni][2], acc[mi][ni][3],
                             a[mi][0], a[mi][1], a[mi][2], a[mi][3],
                             b[ni][0], b[ni][1]);
        }

        if (pre) {
            float* Ad = As + ((it + 1) & 1) * 4104;
            float* Bd = Bs + ((it + 1) & 1) * 4224;
            #pragma unroll
            for (int p = 0; p < 2; p++) {
                float* d = Ad + a_ch * CSA + (a_m + 64 * p) * 8;
                float v0[4] = {ar[p][0].x, ar[p][0].y, ar[p][0].z, ar[p][0].w};
                float v1[4] = {ar[p][1].x, ar[p][1].y, ar[p][1].z, ar[p][1].w};
                #pragma unroll
                for (int j = 0; j < 4; j++) {
                    float2 t; t.x = tf(v0[j]); t.y = tf(v1[j]);
                    *(float2*)(d + 2 * j) = t;
                }
            }
            #pragma unroll
            for (int p = 0; p < 4; p++) {
                float* d = Bd + p * CSB + b_kk * RSB + b_cg * 4;
                float4 t;
                t.x = tf(br[p].x); t.y = tf(br[p].y); t.z = tf(br[p].z); t.w = tf(br[p].w);
                *(float4*)d = t;
            }
            __syncthreads();
        }
    }

    // epilogue
    #pragma unroll
    for (int mi = 0; mi < 4; mi++) {
        int r0 = by * 128 + wm * 64 + mi * 16 + (lane >> 2);
        #pragma unroll
        for (int ni = 0; ni < 4; ni++) {
            int n = bx * 128 + wn * 32 + ni * 8 + 2 * (lane & 3);
            float bz0 = bias[n], bz1 = bias[n + 1];
            float2 t0, t1;
            t0.x = acc[mi][ni][0] + bz0; t0.y = acc[mi][ni][1] + bz1;
            t1.x = acc[mi][ni][2] + bz0; t1.y = acc[mi][ni][3] + bz1;
            if (SPLIT) {
                int bb = r0 >> 11, s = r0 & 2047;
                int h = n >> 6, d = n & 63;
                long base = (((long)(bb * H_ + h)) * S_ + s) * D_ + d;
                *(float2*)(C + base) = t0;
                *(float2*)(C + base + 8 * D_) = t1;
            } else {
                *(float2*)(C + (long)r0 * DM + n) = t0;
                *(float2*)(C + (long)(r0 + 8) * DM + n) = t1;
            }
        }
    }
}

// ---------------------------------------------------------------------------
// K2: per (b,h): scores[S,S] = Q[S,64] @ K[S,64]^T * (1/8)   (tf32 MMA)
// BM=128 BN=128 K=64 (single shot, 8 chunks). Both operands K-major.
// ---------------------------------------------------------------------------
__global__ __launch_bounds__(256)
void scores_tc(const float* __restrict__ Qh, const float* __restrict__ Kh,
               float* __restrict__ attn)
{
    extern __shared__ float sm[];
    float* Qs = sm;            // 8*CSA = 8208
    float* Ks = sm + 8208;

    const int tid = threadIdx.x, lane = tid & 31, warp = tid >> 5;
    const int wm = warp >> 2, wn = warp & 3;
    const int bh = blockIdx.z;
    const float* Qb = Qh + ((long)bh * S_ + (long)blockIdx.y * 128) * D_;
    const float* Kb = Kh + ((long)bh * S_ + (long)blockIdx.x * 128) * D_;

    const int ch = tid & 7, m = tid >> 3;   // 32 rows/pass, 4 passes
    #pragma unroll
    for (int p = 0; p < 4; p++) {
        int row = m + 32 * p;
        const float* sq = Qb + (long)row * 64 + ch * 8;
        float4 q0 = *(const float4*)sq, q1 = *(const float4*)(sq + 4);
        float* dq = Qs + ch * CSA + row * 8;
        const float* sk = Kb + (long)row * 64 + ch * 8;
        float4 k0 = *(const float4*)sk, k1 = *(const float4*)(sk + 4);
        float* dk = Ks + ch * CSA + row * 8;
        float q0a[4] = {q0.x, q0.y, q0.z, q0.w}, q1a[4] = {q1.x, q1.y, q1.z, q1.w};
        float k0a[4] = {k0.x, k0.y, k0.z, k0.w}, k1a[4] = {k1.x, k1.y, k1.z, k1.w};
        #pragma unroll
        for (int j = 0; j < 4; j++) {
            float2 t;
            t.x = tf(q0a[j]); t.y = tf(q1a[j]); *(float2*)(dq + 2 * j) = t;
            t.x = tf(k0a[j]); t.y = tf(k1a[j]); *(float2*)(dk + 2 * j) = t;
        }
    }
    __syncthreads();

    float acc[4][4][4];
    #pragma unroll
    for (int i = 0; i < 4; i++)
        #pragma unroll
        for (int j = 0; j < 4; j++)
            #pragma unroll
            for (int q = 0; q < 4; q++) acc[i][j][q] = 0.f;

    #pragma unroll
    for (int c = 0; c < 8; c++) {
        unsigned a[4][4], b[4][2];
        #pragma unroll
        for (int mi = 0; mi < 4; mi++) {
            int r = wm * 64 + mi * 16 + (lane >> 2);
            float2 lo = *(const float2*)(Qs + c * CSA + r * 8 + 2 * (lane & 3));
            float2 hi = *(const float2*)(Qs + c * CSA + (r + 8) * 8 + 2 * (lane & 3));
            a[mi][0] = __float_as_uint(lo.x); a[mi][1] = __float_as_uint(hi.x);
            a[mi][2] = __float_as_uint(lo.y); a[mi][3] = __float_as_uint(hi.y);
        }
        #pragma unroll
        for (int ni = 0; ni < 4; ni++) {
            int n = wn * 32 + ni * 8 + (lane >> 2);
            float2 v = *(const float2*)(Ks + c * CSA + n * 8 + 2 * (lane & 3));
            b[ni][0] = __float_as_uint(v.x);
            b[ni][1] = __float_as_uint(v.y);
        }
        #pragma unroll
        for (int mi = 0; mi < 4; mi++)
            #pragma unroll
            for (int ni = 0; ni < 4; ni++)
                mma_tf32(acc[mi][ni][0], acc[mi][ni][1], acc[mi][ni][2], acc[mi][ni][3],
                         a[mi][0], a[mi][1], a[mi][2], a[mi][3],
                         b[ni][0], b[ni][1]);
    }

    float* Cb = attn + (long)bh * S_ * S_;
    #pragma unroll
    for (int mi = 0; mi < 4; mi++) {
        int r0 = blockIdx.y * 128 + wm * 64 + mi * 16 + (lane >> 2);
        #pragma unroll
        for (int ni = 0; ni < 4; ni++) {
            int n = blockIdx.x * 128 + wn * 32 + ni * 8 + 2 * (lane & 3);
            float2 t0, t1;
            t0.x = acc[mi][ni][0] * 0.125f; t0.y = acc[mi][ni][1] * 0.125f;
            t1.x = acc[mi][ni][2] * 0.125f; t1.y = acc[mi][ni][3] * 0.125f;
            *(float2*)(Cb + (long)r0 * S_ + n) = t0;
            *(float2*)(Cb + (long)(r0 + 8) * S_ + n) = t1;
        }
    }
}

// ---------------------------------------------------------------------------
// K3: row softmax over attn, with mask (mask==1 -> -1e9), in place.
// ---------------------------------------------------------------------------
__global__ __launch_bounds__(256)
void softmax_kernel(float* __restrict__ attn, const float* __restrict__ mask) {
    const long row = blockIdx.x;
    const int b = (int)(row >> 15);
    float* p = attn + row * S_;
    const float* mrow = mask + (long)b * S_;
    const int tid = threadIdx.x;

    float vals[8];
    #pragma unroll
    for (int l = 0; l < 2; l++) {
        float4 x  = reinterpret_cast<const float4*>(p)[tid + l*256];
        float4 mm = reinterpret_cast<const float4*>(mrow)[tid + l*256];
        vals[l*4+0] = x.x - 1e9f * mm.x;
        vals[l*4+1] = x.y - 1e9f * mm.y;
        vals[l*4+2] = x.z - 1e9f * mm.z;
        vals[l*4+3] = x.w - 1e9f * mm.w;
    }
    float mx = -3.0e38f;
    #pragma unroll
    for (int i = 0; i < 8; i++) mx = fmaxf(mx, vals[i]);

    __shared__ float red[8];
    #pragma unroll
    for (int o = 16; o > 0; o >>= 1) mx = fmaxf(mx, __shfl_xor_sync(0xFFFFFFFFu, mx, o));
    if ((tid & 31) == 0) red[tid >> 5] = mx;
    __syncthreads();
    if (tid < 32) {
        float m2 = (tid < 8) ? red[tid] : -3.0e38f;
        #pragma unroll
        for (int o = 4; o > 0; o >>= 1) m2 = fmaxf(m2, __shfl_xor_sync(0xFFFFFFFFu, m2, o));
        if (tid == 0) red[0] = m2;
    }
    __syncthreads();
    mx = red[0];
    __syncthreads();

    float sum = 0.f;
    #pragma unroll
    for (int i = 0; i < 8; i++) { vals[i] = __expf(vals[i] - mx); sum += vals[i]; }
    #pragma unroll
    for (int o = 16; o > 0; o >>= 1) sum += __shfl_xor_sync(0xFFFFFFFFu, sum, o);
    if ((tid & 31) == 0) red[tid >> 5] = sum;
    __syncthreads();
    if (tid < 32) {
        float s2 = (tid < 8) ? red[tid] : 0.f;
        #pragma unroll
        for (int o = 4; o > 0; o >>= 1) s2 += __shfl_xor_sync(0xFFFFFFFFu, s2, o);
        if (tid == 0) red[0] = s2;
    }
    __syncthreads();
    const float inv = 1.f / red[0];

    #pragma unroll
    for (int l = 0; l < 2; l++) {
        float4 x;
        x.x = vals[l*4+0] * inv;
        x.y = vals[l*4+1] * inv;
        x.z = vals[l*4+2] * inv;
        x.w = vals[l*4+3] * inv;
        reinterpret_cast<float4*>(p)[tid + l*256] = x;
    }
}

// ---------------------------------------------------------------------------
// K4: per (b,h): ctx_h[S,64] = attn[S,S] @ V[S,64] (tf32 MMA), merged-heads out
// BM=128 BN=64 BK=32, 8 warps (4M x 2N), warp tile 32x32, K loop 64 iters
// V-side smem: [chunk][kk][68], chunk stride 548
// ---------------------------------------------------------------------------
#define RSV 68
#define CSV 548
__global__ __launch_bounds__(256)
void context_tc(const float* __restrict__ P, const float* __restrict__ Vh,
                float* __restrict__ ctx)
{
    extern __shared__ float sm[];
    float* As = sm;           // 2 bufs * 4104
    float* Bs = sm + 8208;    // 2 bufs * 4*CSV = 2192 each

    const int tid = threadIdx.x, lane = tid & 31, warp = tid >> 5;
    const int wm = warp >> 1, wn = warp & 1;
    const int bh = blockIdx.z;
    const float* Pb = P + (long)bh * S_ * S_ + (long)blockIdx.y * 128 * S_;
    const float* Vb = Vh + (long)bh * S_ * D_;

    const int a_ch = tid & 3, a_m = tid >> 2;
    const int v_cg = tid & 15, v_k = tid >> 4;   // k = v_k + 16p, 2 passes

    float acc[2][4][4];
    #pragma unroll
    for (int i = 0; i < 2; i++)
        #pragma unroll
        for (int j = 0; j < 4; j++)
            #pragma unroll
            for (int q = 0; q < 4; q++) acc[i][j][q] = 0.f;

    float4 ar[2][2], vr[2];

    // prologue LDG k0=0
    #pragma unroll
    for (int p = 0; p < 2; p++) {
        const float* s = Pb + (long)(a_m + 64 * p) * S_ + a_ch * 8;
        ar[p][0] = *(const float4*)s;
        ar[p][1] = *(const float4*)(s + 4);
        vr[p] = *(const float4*)(Vb + (long)(v_k + 16 * p) * 64 + v_cg * 4);
    }
    {
        #pragma unroll
        for (int p = 0; p < 2; p++) {
            float* d = As + a_ch * CSA + (a_m + 64 * p) * 8;
            float v0[4] = {ar[p][0].x, ar[p][0].y, ar[p][0].z, ar[p][0].w};
            float v1[4] = {ar[p][1].x, ar[p][1].y, ar[p][1].z, ar[p][1].w};
            #pragma unroll
            for (int j = 0; j < 4; j++) {
                float2 t; t.x = tf(v0[j]); t.y = tf(v1[j]);
                *(float2*)(d + 2 * j) = t;
            }
            int k = v_k + 16 * p;
            int chv = k >> 3, kk = 2 * (k & 3) + ((k >> 2) & 1);
            float* dv = Bs + chv * CSV + kk * RSV + v_cg * 4;
            float4 t;
            t.x = tf(vr[p].x); t.y = tf(vr[p].y); t.z = tf(vr[p].z); t.w = tf(vr[p].w);
            *(float4*)dv = t;
        }
    }
    __syncthreads();

    const int NK = S_ / 32;   // 64
    for (int it = 0; it < NK; ++it) {
        const bool pre = (it + 1 < NK);
        if (pre) {
            const int k0 = (it + 1) * 32;
            #pragma unroll
            for (int p = 0; p < 2; p++) {
                const float* s = Pb + (long)(a_m + 64 * p) * S_ + k0 + a_ch * 8;
                ar[p][0] = *(const float4*)s;
                ar[p][1] = *(const float4*)(s + 4);
                vr[p] = *(const float4*)(Vb + (long)(k0 + v_k + 16 * p) * 64 + v_cg * 4);
            }
        }

        const float* Ac = As + (it & 1) * 4104;
        const float* Bc = Bs + (it & 1) * 2192;
        #pragma unroll
        for (int ch = 0; ch < 4; ch++) {
            unsigned a[2][4], b[4][2];
            #pragma unroll
            for (int mi = 0; mi < 2; mi++) {
                int r = wm * 32 + mi * 16 + (lane >> 2);
                float2 lo = *(const float2*)(Ac + ch * CSA + r * 8 + 2 * (lane & 3));
                float2 hi = *(const float2*)(Ac + ch * CSA + (r + 8) * 8 + 2 * (lane & 3));
                a[mi][0] = __float_as_uint(lo.x); a[mi][1] = __float_as_uint(hi.x);
                a[mi][2] = __float_as_uint(lo.y); a[mi][3] = __float_as_uint(hi.y);
            }
            #pragma unroll
            for (int ni = 0; ni < 4; ni++) {
                int n = wn * 32 + ni * 8 + (lane >> 2);
                int c2 = 2 * (lane & 3);
                b[ni][0] = __float_as_uint(Bc[ch * CSV + c2 * RSV + n]);
                b[ni][1] = __float_as_uint(Bc[ch * CSV + (c2 + 1) * RSV + n]);
            }
            #pragma unroll
            for (int mi = 0; mi < 2; mi++)
                #pragma unroll
                for (int ni = 0; ni < 4; ni++)
                    mma_tf32(acc[mi][ni][0], acc[mi][ni][1], acc[mi][ni][2], acc[mi][ni][3],
                             a[mi][0], a[mi][1], a[mi][2], a[mi][3],
                             b[ni][0], b[ni][1]);
        }

        if (pre) {
            float* Ad = As + ((it + 1) & 1) * 4104;
            float* Bd = Bs + ((it + 1) & 1) * 2192;
            #pragma unroll
            for (int p = 0; p < 2; p++) {
                float* d = Ad + a_ch * CSA + (a_m + 64 * p) * 8;
                float v0[4] = {ar[p][0].x, ar[p][0].y, ar[p][0].z, ar[p][0].w};
                float v1[4] = {ar[p][1].x, ar[p][1].y, ar[p][1].z, ar[p][1].w};
                #pragma unroll
                for (int j = 0; j < 4; j++) {
                    float2 t; t.x = tf(v0[j]); t.y = tf(v1[j]);
                    *(float2*)(d + 2 * j) = t;
                }
                int k = v_k + 16 * p;
                int chv = k >> 3, kk = 2 * (k & 3) + ((k >> 2) & 1);
                float* dv = Bd + chv * CSV + kk * RSV + v_cg * 4;
                float4 t;
                t.x = tf(vr[p].x); t.y = tf(vr[p].y); t.z = tf(vr[p].z); t.w = tf(vr[p].w);
                *(float4*)dv = t;
            }
            __syncthreads();
        }
    }

    // epilogue: merged heads layout [B*S, DM], column block h*64
    const int bb = bh >> 4, h = bh & 15;
    #pragma unroll
    for (int mi = 0; mi < 2; mi++) {
        int s = blockIdx.y * 128 + wm * 32 + mi * 16 + (lane >> 2);
        #pragma unroll
        for (int ni = 0; ni < 4; ni++) {
            int d = wn * 32 + ni * 8 + 2 * (lane & 3);
            long base = ((long)bb * S_ + s) * DM + h * 64 + d;
            float2 t0, t1;
            t0.x = acc[mi][ni][0]; t0.y = acc[mi][ni][1];
            t1.x = acc[mi][ni][2]; t1.y = acc[mi][ni][3];
            *(float2*)(ctx + base) = t0;
            *(float2*)(ctx + base + 8 * DM) = t1;
        }
    }
}

// ---------------------------------------------------------------------------
extern "C" void kernel_launch(void* const* d_in, const int* in_sizes, int n_in,
                              void* d_out, int out_size) {
    const float* Q    = (const float*)d_in[0];
    const float* K    = (const float*)d_in[1];
    const float* V    = (const float*)d_in[2];
    const float* mask = (const float*)d_in[3];
    const float* Wq   = (const float*)d_in[4];
    const float* bq   = (const float*)d_in[5];
    const float* Wk   = (const float*)d_in[6];
    const float* bk   = (const float*)d_in[7];
    const float* Wv   = (const float*)d_in[8];
    const float* bv   = (const float*)d_in[9];
    const float* Wo   = (const float*)d_in[10];
    const float* bo   = (const float*)d_in[11];
    float* out = (float*)d_out;

    float *qp, *kp, *vp, *cp, *ap;
    cudaGetSymbolAddress((void**)&qp, g_q);
    cudaGetSymbolAddress((void**)&kp, g_k);
    cudaGetSymbolAddress((void**)&vp, g_v);
    cudaGetSymbolAddress((void**)&cp, g_ctx);
    cudaGetSymbolAddress((void**)&ap, g_attn);

    float* attn = ((long)out_size >= OUT_ELEMS + ATTN_ELEMS) ? (out + OUT_ELEMS) : ap;

    const int SM_GEMM = (8208 + 8448) * 4;         // 66624
    const int SM_SCR  = (8208 + 8208) * 4;         // 65664
    const int SM_CTX  = (8208 + 4384) * 4;         // 50368
    cudaFuncSetAttribute(gemm_tc<0>, cudaFuncAttributeMaxDynamicSharedMemorySize, SM_GEMM);
    cudaFuncSetAttribute(gemm_tc<1>, cudaFuncAttributeMaxDynamicSharedMemorySize, SM_GEMM);
    cudaFuncSetAttribute(scores_tc,  cudaFuncAttributeMaxDynamicSharedMemorySize, SM_SCR);
    cudaFuncSetAttribute(context_tc, cudaFuncAttributeMaxDynamicSharedMemorySize, SM_CTX);

    dim3 g1(DM / 128, MTOT / 128);
    gemm_tc<1><<<g1, 256, SM_GEMM>>>(Q, Wq, bq, qp);
    gemm_tc<1><<<g1, 256, SM_GEMM>>>(K, Wk, bk, kp);
    gemm_tc<1><<<g1, 256, SM_GEMM>>>(V, Wv, bv, vp);

    dim3 g2(S_ / 128, S_ / 128, B_ * H_);
    scores_tc<<<g2, 256, SM_SCR>>>(qp, kp, attn);

    softmax_kernel<<<B_ * H_ * S_, 256>>>(attn, mask);

    dim3 g4(1, S_ / 128, B_ * H_);
    context_tc<<<g4, 256, SM_CTX>>>(attn, vp, cp);

    gemm_tc<0><<<g1, 256, SM_GEMM>>>(cp, Wo, bo, out);
}

// round 3
// speedup vs baseline: 2.4521x; 1.0054x over previous
#include <cuda_runtime.h>
#include <cuda_bf16.h>

// Problem constants
#define B_    2
#define H_    16
#define S_    2048
#define D_    64
#define DM    1024
#define MTOT  4096   // B_*S_

static const long OUT_ELEMS  = (long)MTOT * DM;            // 4,194,304
static const long ATTN_ELEMS = (long)B_ * H_ * S_ * S_;    // 134,217,728

// Scratch (device-global; no runtime allocation allowed)
__device__ float g_q[B_*H_*S_*D_];
__device__ float g_k[B_*H_*S_*D_];
__device__ float g_v[B_*H_*S_*D_];
__device__ float g_ctx[MTOT*DM];
__device__ float g_attn[(size_t)B_*H_*S_*S_];
__device__ float g_inv[B_*H_*S_];   // per-row 1/sum(exp)

// ---------------------------------------------------------------------------
// tf32 helpers
// ---------------------------------------------------------------------------
__device__ __forceinline__ float tf(float f) {
    unsigned u;
    asm("cvt.rna.tf32.f32 %0, %1;" : "=r"(u) : "f"(f));
    return __uint_as_float(u);
}

__device__ __forceinline__ void mma_tf32(
    float& c0, float& c1, float& c2, float& c3,
    unsigned a0, unsigned a1, unsigned a2, unsigned a3,
    unsigned b0, unsigned b1)
{
    asm volatile(
        "mma.sync.aligned.m16n8k8.row.col.f32.tf32.tf32.f32 "
        "{%0,%1,%2,%3},{%4,%5,%6,%7},{%8,%9},{%0,%1,%2,%3};"
        : "+f"(c0), "+f"(c1), "+f"(c2), "+f"(c3)
        : "r"(a0), "r"(a1), "r"(a2), "r"(a3), "r"(b0), "r"(b1));
}

// A-style interleaved layout: [chunk][row][8], chunk stride 1026 floats
#define CSA 1026
// W/V-style layout: [chunk][kk][stride], for dense gemm RSB=132 CSB=1056
#define RSB 132
#define CSB 1056
// V tile (d=64): [chunk][kk][68], chunk stride 548
#define RSV 68
#define CSV 548

// ---------------------------------------------------------------------------
// K1/K5: C[4096,1024] = A[4096,1024] @ W[1024,1024] + bias   (tf32 MMA)
// ---------------------------------------------------------------------------
template<int SPLIT>
__global__ __launch_bounds__(256)
void gemm_tc(const float* __restrict__ A, const float* __restrict__ W,
             const float* __restrict__ bias, float* __restrict__ C)
{
    extern __shared__ float sm[];
    float* As = sm;           // 2 bufs * 4*CSA = 8208
    float* Bs = sm + 8208;    // 2 bufs * 4*CSB = 8448

    const int tid = threadIdx.x, lane = tid & 31, warp = tid >> 5;
    const int wm = warp >> 2, wn = warp & 3;
    const int bx = blockIdx.x, by = blockIdx.y;
    const float* Ab = A + (long)by * 128 * DM;
    const float* Wb = W + (long)bx * 128;

    const int a_ch = tid & 3, a_m = tid >> 2;
    const int b_cg = tid & 31, b_k = tid >> 5;

    float acc[4][4][4];
    #pragma unroll
    for (int i = 0; i < 4; i++)
        #pragma unroll
        for (int j = 0; j < 4; j++)
            #pragma unroll
            for (int q = 0; q < 4; q++) acc[i][j][q] = 0.f;

    float4 ar[2][2], br[4];
    const int b_kk = 2 * (b_k & 3) + ((b_k >> 2) & 1);

    #pragma unroll
    for (int p = 0; p < 2; p++) {
        const float* s = Ab + (long)(a_m + 64 * p) * DM + a_ch * 8;
        ar[p][0] = *(const float4*)s;
        ar[p][1] = *(const float4*)(s + 4);
    }
    #pragma unroll
    for (int p = 0; p < 4; p++)
        br[p] = *(const float4*)(Wb + (long)(b_k + 8 * p) * DM + b_cg * 4);

    {
        #pragma unroll
        for (int p = 0; p < 2; p++) {
            float* d = As + a_ch * CSA + (a_m + 64 * p) * 8;
            float v0[4] = {ar[p][0].x, ar[p][0].y, ar[p][0].z, ar[p][0].w};
            float v1[4] = {ar[p][1].x, ar[p][1].y, ar[p][1].z, ar[p][1].w};
            #pragma unroll
            for (int j = 0; j < 4; j++) {
                float2 t; t.x = tf(v0[j]); t.y = tf(v1[j]);
                *(float2*)(d + 2 * j) = t;
            }
        }
        #pragma unroll
        for (int p = 0; p < 4; p++) {
            float* d = Bs + p * CSB + b_kk * RSB + b_cg * 4;
            float4 t;
            t.x = tf(br[p].x); t.y = tf(br[p].y); t.z = tf(br[p].z); t.w = tf(br[p].w);
            *(float4*)d = t;
        }
    }
    __syncthreads();

    const int NK = DM / 32;
    for (int it = 0; it < NK; ++it) {
        const bool pre = (it + 1 < NK);
        if (pre) {
            const int k0 = (it + 1) * 32;
            #pragma unroll
            for (int p = 0; p < 2; p++) {
                const float* s = Ab + (long)(a_m + 64 * p) * DM + k0 + a_ch * 8;
                ar[p][0] = *(const float4*)s;
                ar[p][1] = *(const float4*)(s + 4);
            }
            #pragma unroll
            for (int p = 0; p < 4; p++)
                br[p] = *(const float4*)(Wb + (long)(k0 + b_k + 8 * p) * DM + b_cg * 4);
        }

        const float* Ac = As + (it & 1) * 4104;
        const float* Bc = Bs + (it & 1) * 4224;
        #pragma unroll
        for (int ch = 0; ch < 4; ch++) {
            unsigned a[4][4], b[4][2];
            #pragma unroll
            for (int mi = 0; mi < 4; mi++) {
                int r = wm * 64 + mi * 16 + (lane >> 2);
                float2 lo = *(const float2*)(Ac + ch * CSA + r * 8 + 2 * (lane & 3));
                float2 hi = *(const float2*)(Ac + ch * CSA + (r + 8) * 8 + 2 * (lane & 3));
                a[mi][0] = __float_as_uint(lo.x); a[mi][1] = __float_as_uint(hi.x);
                a[mi][2] = __float_as_uint(lo.y); a[mi][3] = __float_as_uint(hi.y);
            }
            #pragma unroll
            for (int ni = 0; ni < 4; ni++) {
                int n = wn * 32 + ni * 8 + (lane >> 2);
                int c2 = 2 * (lane & 3);
                b[ni][0] = __float_as_uint(Bc[ch * CSB + c2 * RSB + n]);
                b[ni][1] = __float_as_uint(Bc[ch * CSB + (c2 + 1) * RSB + n]);
            }
            #pragma unroll
            for (int mi = 0; mi < 4; mi++)
                #pragma unroll
                for (int ni = 0; ni < 4; ni++)
                    mma_tf32(acc[mi][ni][0], acc[mi][ni][1], acc[mi][ni][2], acc[mi][ni][3],
                             a[mi][0], a[mi][1], a[mi][2], a[mi][3],
                             b[ni][0], b[ni][1]);
        }

        if (pre) {
            float* Ad = As + ((it + 1) & 1) * 4104;
            float* Bd = Bs + ((it + 1) & 1) * 4224;
            #pragma unroll
            for (int p = 0; p < 2; p++) {
                float* d = Ad + a_ch * CSA + (a_m + 64 * p) * 8;
                float v0[4] = {ar[p][0].x, ar[p][0].y, ar[p][0].z, ar[p][0].w};
                float v1[4] = {ar[p][1].x, ar[p][1].y, ar[p][1].z, ar[p][1].w};
                #pragma unroll
                for (int j = 0; j < 4; j++) {
                    float2 t; t.x = tf(v0[j]); t.y = tf(v1[j]);
                    *(float2*)(d + 2 * j) = t;
                }
            }
            #pragma unroll
            for (int p = 0; p < 4; p++) {
                float* d = Bd + p * CSB + b_kk * RSB + b_cg * 4;
                float4 t;
                t.x = tf(br[p].x); t.y = tf(br[p].y); t.z = tf(br[p].z); t.w = tf(br[p].w);
                *(float4*)d = t;
            }
            __syncthreads();
        }
    }

    #pragma unroll
    for (int mi = 0; mi < 4; mi++) {
        int r0 = by * 128 + wm * 64 + mi * 16 + (lane >> 2);
        #pragma unroll
        for (int ni = 0; ni < 4; ni++) {
            int n = bx * 128 + wn * 32 + ni * 8 + 2 * (lane & 3);
            float bz0 = bias[n], bz1 = bias[n + 1];
            float2 t0, t1;
            t0.x = acc[mi][ni][0] + bz0; t0.y = acc[mi][ni][1] + bz1;
            t1.x = acc[mi][ni][2] + bz0; t1.y = acc[mi][ni][3] + bz1;
            if (SPLIT) {
                int bb = r0 >> 11, s = r0 & 2047;
                int h = n >> 6, d = n & 63;
                long base = (((long)(bb * H_ + h)) * S_ + s) * D_ + d;
                *(float2*)(C + base) = t0;
                *(float2*)(C + base + 8 * D_) = t1;
            } else {
                *(float2*)(C + (long)r0 * DM + n) = t0;
                *(float2*)(C + (long)(r0 + 8) * DM + n) = t1;
            }
        }
    }
}

// ---------------------------------------------------------------------------
// K2: scores + online row-sum-of-exp.
// Per CTA: 128 query rows of one (b,h); sweep all 2048 keys in 16 tiles.
// Writes raw masked/scaled scores to gmem, writes inv[row] = 1/sum(exp).
// Warps: 2m x 4n, warp tile 64x32. Q frags for mi=0,1 cached in registers.
// ---------------------------------------------------------------------------
__global__ __launch_bounds__(256, 1)
void scores_sum_tc(const float* __restrict__ Qh, const float* __restrict__ Kh,
                   const float* __restrict__ mask,
                   float* __restrict__ raw, float* __restrict__ inv_out)
{
    extern __shared__ float sm[];
    float* Qs  = sm;                 // 8208
    float* Ks  = sm + 8208;          // 2 * 8208
    float* msk = sm + 3 * 8208;      // 2048
    float* red = msk + 2048;         // 512

    const int tid = threadIdx.x, lane = tid & 31, warp = tid >> 5;
    const int wm = warp >> 2, wn = warp & 3;
    const int bh = blockIdx.z;
    const int row0 = blockIdx.x * 128;
    const float* Qb = Qh + ((long)bh * S_ + row0) * D_;
    const float* Kb = Kh + (long)bh * S_ * D_;
    float* rawb = raw + (long)bh * S_ * S_ + (long)row0 * S_;
    const int bb = bh >> 4;

    // mask -> smem
    #pragma unroll
    for (int i = tid; i < 512; i += 256)
        ((float4*)msk)[i] = ((const float4*)(mask + (long)bb * S_))[i];

    // Q -> smem (interleaved A layout), K tile 0 -> smem
    const int ch = tid & 7, m = tid >> 3;
    #pragma unroll
    for (int p = 0; p < 4; p++) {
        int row = m + 32 * p;
        const float* sq = Qb + (long)row * D_ + ch * 8;
        float4 q0 = *(const float4*)sq, q1 = *(const float4*)(sq + 4);
        float* dq = Qs + ch * CSA + row * 8;
        const float* sk = Kb + (long)row * D_ + ch * 8;
        float4 k0 = *(const float4*)sk, k1 = *(const float4*)(sk + 4);
        float* dk = Ks + ch * CSA + row * 8;
        float q0a[4] = {q0.x,q0.y,q0.z,q0.w}, q1a[4] = {q1.x,q1.y,q1.z,q1.w};
        float k0a[4] = {k0.x,k0.y,k0.z,k0.w}, k1a[4] = {k1.x,k1.y,k1.z,k1.w};
        #pragma unroll
        for (int j = 0; j < 4; j++) {
            float2 t;
            t.x = tf(q0a[j]); t.y = tf(q1a[j]); *(float2*)(dq + 2*j) = t;
            t.x = tf(k0a[j]); t.y = tf(k1a[j]); *(float2*)(dk + 2*j) = t;
        }
    }
    __syncthreads();

    // Cache Q fragments for mi=0,1 in registers
    unsigned qf[2][8][4];
    #pragma unroll
    for (int mi = 0; mi < 2; mi++)
        #pragma unroll
        for (int c = 0; c < 8; c++) {
            int r = wm * 64 + mi * 16 + (lane >> 2);
            float2 lo = *(const float2*)(Qs + c * CSA + r * 8 + 2 * (lane & 3));
            float2 hi = *(const float2*)(Qs + c * CSA + (r + 8) * 8 + 2 * (lane & 3));
            qf[mi][c][0] = __float_as_uint(lo.x); qf[mi][c][1] = __float_as_uint(hi.x);
            qf[mi][c][2] = __float_as_uint(lo.y); qf[mi][c][3] = __float_as_uint(hi.y);
        }

    float ssum[8];
    #pragma unroll
    for (int i = 0; i < 8; i++) ssum[i] = 0.f;

    float4 kr[8];
    float acc[4][4][4];

    for (int kt = 0; kt < 16; ++kt) {
        const bool pre = (kt + 1 < 16);
        if (pre) {
            #pragma unroll
            for (int p = 0; p < 4; p++) {
                int row = (kt + 1) * 128 + m + 32 * p;
                const float* sk = Kb + (long)row * D_ + ch * 8;
                kr[2*p]   = *(const float4*)sk;
                kr[2*p+1] = *(const float4*)(sk + 4);
            }
        }

        #pragma unroll
        for (int i = 0; i < 4; i++)
            #pragma unroll
            for (int j = 0; j < 4; j++)
                #pragma unroll
                for (int q = 0; q < 4; q++) acc[i][j][q] = 0.f;

        const float* Kc = Ks + (kt & 1) * 8208;
        #pragma unroll
        for (int c = 0; c < 8; c++) {
            unsigned a2[2][4], b[4][2];
            #pragma unroll
            for (int mi = 0; mi < 2; mi++) {
                int r = wm * 64 + (mi + 2) * 16 + (lane >> 2);
                float2 lo = *(const float2*)(Qs + c * CSA + r * 8 + 2 * (lane & 3));
                float2 hi = *(const float2*)(Qs + c * CSA + (r + 8) * 8 + 2 * (lane & 3));
                a2[mi][0] = __float_as_uint(lo.x); a2[mi][1] = __float_as_uint(hi.x);
                a2[mi][2] = __float_as_uint(lo.y); a2[mi][3] = __float_as_uint(hi.y);
            }
            #pragma unroll
            for (int ni = 0; ni < 4; ni++) {
                int n = wn * 32 + ni * 8 + (lane >> 2);
                float2 v = *(const float2*)(Kc + c * CSA + n * 8 + 2 * (lane & 3));
                b[ni][0] = __float_as_uint(v.x);
                b[ni][1] = __float_as_uint(v.y);
            }
            #pragma unroll
            for (int mi = 0; mi < 4; mi++) {
                const unsigned* a = (mi < 2) ? qf[mi][c] : a2[mi - 2];
                #pragma unroll
                for (int ni = 0; ni < 4; ni++)
                    mma_tf32(acc[mi][ni][0], acc[mi][ni][1], acc[mi][ni][2], acc[mi][ni][3],
                             a[0], a[1], a[2], a[3], b[ni][0], b[ni][1]);
            }
        }

        // epilogue for this tile: scale, mask, write raw, accumulate exp sums
        #pragma unroll
        for (int mi = 0; mi < 4; mi++) {
            int r = wm * 64 + mi * 16 + (lane >> 2);
            #pragma unroll
            for (int ni = 0; ni < 4; ni++) {
                int n = kt * 128 + wn * 32 + ni * 8 + 2 * (lane & 3);
                float2 mm = *(const float2*)(msk + n);
                float x0 = fmaf(acc[mi][ni][0], 0.125f, -1e9f * mm.x);
                float x1 = fmaf(acc[mi][ni][1], 0.125f, -1e9f * mm.y);
                float x2 = fmaf(acc[mi][ni][2], 0.125f, -1e9f * mm.x);
                float x3 = fmaf(acc[mi][ni][3], 0.125f, -1e9f * mm.y);
                float2 t0; t0.x = x0; t0.y = x1;
                float2 t1; t1.x = x2; t1.y = x3;
                *(float2*)(rawb + (long)r * S_ + n) = t0;
                *(float2*)(rawb + (long)(r + 8) * S_ + n) = t1;
                ssum[mi*2]   += __expf(x0) + __expf(x1);
                ssum[mi*2+1] += __expf(x2) + __expf(x3);
            }
        }

        if (pre) {
            float* Kd = Ks + ((kt + 1) & 1) * 8208;
            #pragma unroll
            for (int p = 0; p < 4; p++) {
                int row = m + 32 * p;
                float* dk = Kd + ch * CSA + row * 8;
                float k0a[4] = {kr[2*p].x, kr[2*p].y, kr[2*p].z, kr[2*p].w};
                float k1a[4] = {kr[2*p+1].x, kr[2*p+1].y, kr[2*p+1].z, kr[2*p+1].w};
                #pragma unroll
                for (int j = 0; j < 4; j++) {
                    float2 t; t.x = tf(k0a[j]); t.y = tf(k1a[j]);
                    *(float2*)(dk + 2*j) = t;
                }
            }
            __syncthreads();
        }
    }

    // reduce sums: across quad lanes, then across wn warps via smem
    #pragma unroll
    for (int i = 0; i < 8; i++) {
        ssum[i] += __shfl_xor_sync(0xFFFFFFFFu, ssum[i], 1);
        ssum[i] += __shfl_xor_sync(0xFFFFFFFFu, ssum[i], 2);
    }
    if ((lane & 3) == 0) {
        #pragma unroll
        for (int mi = 0; mi < 4; mi++)
            #pragma unroll
            for (int h = 0; h < 2; h++) {
                int r = wm * 64 + mi * 16 + (lane >> 2) + 8 * h;
                red[wn * 128 + r] = ssum[mi * 2 + h];
            }
    }
    __syncthreads();
    if (tid < 128) {
        float s = red[tid] + red[128 + tid] + red[256 + tid] + red[384 + tid];
        inv_out[(long)bh * S_ + row0 + tid] = 1.0f / s;
    }
}

// ---------------------------------------------------------------------------
// K3: fused normalize + attn write + P@V context.
// Per CTA: 128 rows of one (b,h); 32 tiles of 64 keys.
// Reads raw scores, p = exp(x)*inv, writes normalized attn in place,
// stages p (tf32) in smem and accumulates ctx = P@V. Warps 4m x 2n.
// ---------------------------------------------------------------------------
__global__ __launch_bounds__(256)
void ctx_attn_tc(float* __restrict__ attn, const float* __restrict__ Vh,
                 const float* __restrict__ inv_in, float* __restrict__ ctx)
{
    extern __shared__ float sm[];
    float* Ps   = sm;                 // 2 * 8208
    float* Vs   = sm + 2 * 8208;      // 2 * 4384
    float* invs = sm + 2 * 8208 + 2 * 4384;  // 128

    const int tid = threadIdx.x, lane = tid & 31, warp = tid >> 5;
    const int wm = warp >> 1, wn = warp & 1;
    const int bh = blockIdx.z;
    const int row0 = blockIdx.x * 128;
    float* rawb = attn + (long)bh * S_ * S_ + (long)row0 * S_;
    const float* Vb = Vh + (long)bh * S_ * D_;

    if (tid < 128) invs[tid] = inv_in[(long)bh * S_ + row0 + tid];
    __syncthreads();

    const int c16 = tid & 15, rl = tid >> 4;   // raw loader
    const int vcg = tid & 15, vk = tid >> 4;   // V loader
    const int pch = c16 >> 1;                  // P chunk for this thread
    const int podd = (c16 & 1);                // pos parity

    float4 rr[8], vr[4];

    // prologue: load tile 0
    #pragma unroll
    for (int p = 0; p < 8; p++) {
        int row = rl + 16 * p;
        rr[p] = *(const float4*)(rawb + (long)row * S_ + c16 * 4);
    }
    #pragma unroll
    for (int p = 0; p < 4; p++)
        vr[p] = *(const float4*)(Vb + (long)(vk + 16 * p) * D_ + vcg * 4);

    // process tile 0 into buf 0
    {
        float* Pd = Ps;
        float* Vd = Vs;
        #pragma unroll
        for (int p = 0; p < 8; p++) {
            int row = rl + 16 * p;
            float iv = invs[row];
            float4 e;
            e.x = __expf(rr[p].x) * iv;
            e.y = __expf(rr[p].y) * iv;
            e.z = __expf(rr[p].z) * iv;
            e.w = __expf(rr[p].w) * iv;
            *(float4*)(rawb + (long)row * S_ + c16 * 4) = e;
            float ev[4] = {e.x, e.y, e.z, e.w};
            float* d = Pd + pch * CSA + row * 8 + podd;
            #pragma unroll
            for (int j = 0; j < 4; j++) d[2 * j] = tf(ev[j]);
        }
        #pragma unroll
        for (int p = 0; p < 4; p++) {
            int key = vk + 16 * p;
            int chv = key >> 3, kk = 2 * (key & 3) + ((key >> 2) & 1);
            float4 t;
            t.x = tf(vr[p].x); t.y = tf(vr[p].y); t.z = tf(vr[p].z); t.w = tf(vr[p].w);
            *(float4*)(Vd + chv * CSV + kk * RSV + vcg * 4) = t;
        }
    }
    __syncthreads();

    float acc[2][4][4];
    #pragma unroll
    for (int i = 0; i < 2; i++)
        #pragma unroll
        for (int j = 0; j < 4; j++)
            #pragma unroll
            for (int q = 0; q < 4; q++) acc[i][j][q] = 0.f;

    const int NT = S_ / 64;   // 32
    for (int kt = 0; kt < NT; ++kt) {
        const bool pre = (kt + 1 < NT);
        if (pre) {
            const int k0 = (kt + 1) * 64;
            #pragma unroll
            for (int p = 0; p < 8; p++) {
                int row = rl + 16 * p;
                rr[p] = *(const float4*)(rawb + (long)row * S_ + k0 + c16 * 4);
            }
            #pragma unroll
            for (int p = 0; p < 4; p++)
                vr[p] = *(const float4*)(Vb + (long)(k0 + vk + 16 * p) * D_ + vcg * 4);
        }

        const float* Pc = Ps + (kt & 1) * 8208;
        const float* Vc = Vs + (kt & 1) * 4384;
        #pragma unroll
        for (int c = 0; c < 8; c++) {
            unsigned a[2][4], b[4][2];
            #pragma unroll
            for (int mi = 0; mi < 2; mi++) {
                int r = wm * 32 + mi * 16 + (lane >> 2);
                float2 lo = *(const float2*)(Pc + c * CSA + r * 8 + 2 * (lane & 3));
                float2 hi = *(const float2*)(Pc + c * CSA + (r + 8) * 8 + 2 * (lane & 3));
                a[mi][0] = __float_as_uint(lo.x); a[mi][1] = __float_as_uint(hi.x);
                a[mi][2] = __float_as_uint(lo.y); a[mi][3] = __float_as_uint(hi.y);
            }
            #pragma unroll
            for (int ni = 0; ni < 4; ni++) {
                int n = wn * 32 + ni * 8 + (lane >> 2);
                int c2 = 2 * (lane & 3);
                b[ni][0] = __float_as_uint(Vc[c * CSV + c2 * RSV + n]);
                b[ni][1] = __float_as_uint(Vc[c * CSV + (c2 + 1) * RSV + n]);
            }
            #pragma unroll
            for (int mi = 0; mi < 2; mi++)
                #pragma unroll
                for (int ni = 0; ni < 4; ni++)
                    mma_tf32(acc[mi][ni][0], acc[mi][ni][1], acc[mi][ni][2], acc[mi][ni][3],
                             a[mi][0], a[mi][1], a[mi][2], a[mi][3],
                             b[ni][0], b[ni][1]);
        }

        if (pre) {
            const int k0 = (kt + 1) * 64;
            float* Pd = Ps + ((kt + 1) & 1) * 8208;
            float* Vd = Vs + ((kt + 1) & 1) * 4384;
            #pragma unroll
            for (int p = 0; p < 8; p++) {
                int row = rl + 16 * p;
                float iv = invs[row];
                float4 e;
                e.x = __expf(rr[p].x) * iv;
                e.y = __expf(rr[p].y) * iv;
                e.z = __expf(rr[p].z) * iv;
                e.w = __expf(rr[p].w) * iv;
                *(float4*)(rawb + (long)row * S_ + k0 + c16 * 4) = e;
                float ev[4] = {e.x, e.y, e.z, e.w};
                float* d = Pd + pch * CSA + row * 8 + podd;
                #pragma unroll
                for (int j = 0; j < 4; j++) d[2 * j] = tf(ev[j]);
            }
            #pragma unroll
            for (int p = 0; p < 4; p++) {
                int key = vk + 16 * p;
                int chv = key >> 3, kk = 2 * (key & 3) + ((key >> 2) & 1);
                float4 t;
                t.x = tf(vr[p].x); t.y = tf(vr[p].y); t.z = tf(vr[p].z); t.w = tf(vr[p].w);
                *(float4*)(Vd + chv * CSV + kk * RSV + vcg * 4) = t;
            }
            __syncthreads();
        }
    }

    // epilogue: merged-heads write
    const int bb = bh >> 4, h = bh & 15;
    #pragma unroll
    for (int mi = 0; mi < 2; mi++) {
        int s = row0 + wm * 32 + mi * 16 + (lane >> 2);
        #pragma unroll
        for (int ni = 0; ni < 4; ni++) {
            int d = wn * 32 + ni * 8 + 2 * (lane & 3);
            long base = ((long)bb * S_ + s) * DM + h * 64 + d;
            float2 t0, t1;
            t0.x = acc[mi][ni][0]; t0.y = acc[mi][ni][1];
            t1.x = acc[mi][ni][2]; t1.y = acc[mi][ni][3];
            *(float2*)(ctx + base) = t0;
            *(float2*)(ctx + base + 8 * DM) = t1;
        }
    }
}

// ---------------------------------------------------------------------------
extern "C" void kernel_launch(void* const* d_in, const int* in_sizes, int n_in,
                              void* d_out, int out_size) {
    const float* Q    = (const float*)d_in[0];
    const float* K    = (const float*)d_in[1];
    const float* V    = (const float*)d_in[2];
    const float* mask = (const float*)d_in[3];
    const float* Wq   = (const float*)d_in[4];
    const float* bq   = (const float*)d_in[5];
    const float* Wk   = (const float*)d_in[6];
    const float* bk   = (const float*)d_in[7];
    const float* Wv   = (const float*)d_in[8];
    const float* bv   = (const float*)d_in[9];
    const float* Wo   = (const float*)d_in[10];
    const float* bo   = (const float*)d_in[11];
    float* out = (float*)d_out;

    float *qp, *kp, *vp, *cp, *ap, *ip;
    cudaGetSymbolAddress((void**)&qp, g_q);
    cudaGetSymbolAddress((void**)&kp, g_k);
    cudaGetSymbolAddress((void**)&vp, g_v);
    cudaGetSymbolAddress((void**)&cp, g_ctx);
    cudaGetSymbolAddress((void**)&ap, g_attn);
    cudaGetSymbolAddress((void**)&ip, g_inv);

    float* attn = ((long)out_size >= OUT_ELEMS + ATTN_ELEMS) ? (out + OUT_ELEMS) : ap;

    const int SM_GEMM = (8208 + 8448) * 4;                    // 66624
    const int SM_SCR  = (3 * 8208 + 2048 + 512) * 4;          // 108736
    const int SM_CTX  = (2 * 8208 + 2 * 4384 + 128) * 4;      // 101248
    cudaFuncSetAttribute(gemm_tc<0>, cudaFuncAttributeMaxDynamicSharedMemorySize, SM_GEMM);
    cudaFuncSetAttribute(gemm_tc<1>, cudaFuncAttributeMaxDynamicSharedMemorySize, SM_GEMM);
    cudaFuncSetAttribute(scores_sum_tc, cudaFuncAttributeMaxDynamicSharedMemorySize, SM_SCR);
    cudaFuncSetAttribute(ctx_attn_tc,   cudaFuncAttributeMaxDynamicSharedMemorySize, SM_CTX);

    dim3 g1(DM / 128, MTOT / 128);
    gemm_tc<1><<<g1, 256, SM_GEMM>>>(Q, Wq, bq, qp);
    gemm_tc<1><<<g1, 256, SM_GEMM>>>(K, Wk, bk, kp);
    gemm_tc<1><<<g1, 256, SM_GEMM>>>(V, Wv, bv, vp);

    dim3 g2(S_ / 128, 1, B_ * H_);
    scores_sum_tc<<<g2, 256, SM_SCR>>>(qp, kp, mask, attn, ip);

    ctx_attn_tc<<<g2, 256, SM_CTX>>>(attn, vp, ip, cp);

    gemm_tc<0><<<g1, 256, SM_GEMM>>>(cp, Wo, bo, out);
}